// round 1
// baseline (speedup 1.0000x reference)
#include <cuda_runtime.h>

// Problem: x (2,128,7,7) fp32 -> causality maps (2,128,128) fp32.
// With p=1 the Lehmer cross-sum is rank-1 separable:
//   sum_ij (xf[m,i]*xf[n,j])   = S[m]*S[n]
//   sum_ij (xf[m,i]*xf[n,j])^2 = Q[m]*Q[n]
// so the whole O(C^2 F^2) einsum reduces to per-channel S,Q + a 128x128 combine.

#define EPS 1e-8f
#define C_CH 128
#define F_SP 49
#define CF (C_CH * F_SP)   // 6272 elems per batch

__global__ __launch_bounds__(1024, 1)
void causality_kernel(const float* __restrict__ x, float* __restrict__ out) {
    const int b   = blockIdx.x;
    const int tid = threadIdx.x;

    __shared__ float sx[CF];       // raw batch slice (25 KB)
    __shared__ float S[C_CH];
    __shared__ float Q[C_CH];
    __shared__ float Ld[C_CH];
    __shared__ float red[32];

    const float* xb = x + b * CF;

    // ---- stage to SMEM + per-thread max (x >= 0 for this input distribution,
    //      but use fmaxf over raw values with -inf-safe init anyway) ----
    float m = -3.402823466e+38f;
    for (int i = tid; i < CF; i += 1024) {
        float v = xb[i];
        sx[i] = v;
        m = fmaxf(m, v);
    }
    // warp reduce
    #pragma unroll
    for (int o = 16; o > 0; o >>= 1)
        m = fmaxf(m, __shfl_xor_sync(0xffffffffu, m, o));
    if ((tid & 31) == 0) red[tid >> 5] = m;
    __syncthreads();
    if (tid < 32) {
        float v = red[tid];
        #pragma unroll
        for (int o = 16; o > 0; o >>= 1)
            v = fmaxf(v, __shfl_xor_sync(0xffffffffu, v, o));
        if (tid == 0) red[0] = v;
    }
    __syncthreads();
    const float inv = 1.0f / (red[0] + EPS);

    // ---- per-channel S, Q, and Lehmer denominator ----
    // thread t reads sx[t*49 + i]: 49 mod 32 = 17, coprime with 32 -> conflict-free
    if (tid < C_CH) {
        float s = 0.0f, q = 0.0f;
        #pragma unroll
        for (int i = 0; i < F_SP; i++) {
            float v = sx[tid * F_SP + i] * inv;   // nan_to_num: inputs finite
            s += v;
            q += v * v;
        }
        S[tid] = s;
        Q[tid] = q;
        // sum_i (a+eps)^2 = Q + 2 eps S + F eps^2 ; sum_i (a+eps) = S + F eps
        float nd = q + 2.0f * EPS * s + (float)F_SP * EPS * EPS + EPS;
        float dd = s + (float)F_SP * EPS + EPS;
        Ld[tid] = nd / dd + EPS;
    }
    __syncthreads();

    // ---- 128x128 combine: out[b,m,n] = LN[m,n] / Ld[n] ----
    const float ff_e2 = (float)(F_SP * F_SP) * EPS * EPS;  // F^2 eps^2
    const float ff_e  = (float)(F_SP * F_SP) * EPS;        // F^2 eps
    float* ob = out + b * (C_CH * C_CH);
    #pragma unroll
    for (int k = 0; k < (C_CH * C_CH) / 1024; k++) {
        int idx = k * 1024 + tid;
        int mm = idx >> 7;
        int nn = idx & 127;
        float ss = S[mm] * S[nn];
        float num = Q[mm] * Q[nn] + 2.0f * EPS * ss + ff_e2 + EPS;
        float den = ss + ff_e + EPS;
        float ln  = num / den + EPS;
        ob[idx] = ln / Ld[nn];
    }
}

extern "C" void kernel_launch(void* const* d_in, const int* in_sizes, int n_in,
                              void* d_out, int out_size) {
    const float* x = (const float*)d_in[0];
    float* out = (float*)d_out;
    // B = total elems / (C*F)
    int B = in_sizes[0] / CF;   // = 2
    causality_kernel<<<B, 1024>>>(x, out);
}

// round 2
// speedup vs baseline: 1.2305x; 1.2305x over previous
#include <cuda_runtime.h>

// x (2,128,7,7) fp32 -> causality maps (2,128,128) fp32.
// p=1 => Lehmer cross-sums are rank-1 separable:
//   sum_ij cross   = S[m]*S[n],  sum_ij cross^2 = Q[m]*Q[n]
// and normalization commutes with the sums: S = S_raw*inv, Q = Q_raw*inv^2.
// Single pass: fused load + max + per-channel S_raw/Q_raw, then 128x128 combine.

#define EPS 1e-8f
#define C_CH 128
#define F_SP 49
#define CF (C_CH * F_SP)

__global__ __launch_bounds__(1024, 1)
void causality_kernel(const float* __restrict__ x, float* __restrict__ out) {
    const int b    = blockIdx.x;
    const int tid  = threadIdx.x;
    const int ch   = tid >> 3;      // channel 0..127
    const int l8   = tid & 7;       // lane within 8-thread channel group

    __shared__ float S[C_CH];
    __shared__ float Q[C_CH];
    __shared__ float invLd[C_CH];
    __shared__ float red[33];

    const float* __restrict__ xc = x + b * CF + ch * F_SP;

    // ---- fused pass: raw max + raw per-channel sum / sum-of-squares ----
    float m = -3.402823466e+38f;
    float s = 0.0f, q = 0.0f;
    #pragma unroll
    for (int i = 0; i < 7; i++) {
        int j = l8 + 8 * i;               // 0..55, mask to 49
        if (j < F_SP) {
            float v = __ldg(xc + j);      // 8 consecutive floats per group/iter
            m = fmaxf(m, v);
            s += v;
            q += v * v;
        }
    }

    // 8-lane reduce for s,q (stays within warp); full-warp reduce for max
    #pragma unroll
    for (int o = 4; o > 0; o >>= 1) {
        s += __shfl_xor_sync(0xffffffffu, s, o);
        q += __shfl_xor_sync(0xffffffffu, q, o);
        m = fmaxf(m, __shfl_xor_sync(0xffffffffu, m, o));
    }
    #pragma unroll
    for (int o = 16; o > 4; o >>= 1)
        m = fmaxf(m, __shfl_xor_sync(0xffffffffu, m, o));

    if ((tid & 31) == 0) red[tid >> 5] = m;
    __syncthreads();
    if (tid < 32) {
        float v = red[tid];
        #pragma unroll
        for (int o = 16; o > 0; o >>= 1)
            v = fmaxf(v, __shfl_xor_sync(0xffffffffu, v, o));
        if (tid == 0) red[32] = v;
    }
    __syncthreads();

    const float inv = __fdividef(1.0f, red[32] + EPS);

    if (l8 == 0) {
        float sn = s * inv;
        float qn = q * inv * inv;
        S[ch] = sn;
        Q[ch] = qn;
        // Ld = (Q + 2*eps*S + F*eps^2 + eps)/(S + F*eps + eps) + eps
        float nd = qn + 2.0f * EPS * sn + (float)F_SP * EPS * EPS + EPS;
        float dd = sn + (float)F_SP * EPS + EPS;
        invLd[ch] = __fdividef(dd, nd + EPS * dd);   // 1/(nd/dd + eps)
    }
    __syncthreads();

    // ---- 128x128 combine: out[m,n] = (num/den + eps) * invLd[n] ----
    const float ff_e2 = (float)(F_SP * F_SP) * EPS * EPS;
    const float ff_e  = (float)(F_SP * F_SP) * EPS;
    float* __restrict__ ob = out + b * (C_CH * C_CH);
    #pragma unroll
    for (int k = 0; k < (C_CH * C_CH) / 1024; k++) {
        int idx = k * 1024 + tid;
        int mm = idx >> 7;
        int nn = idx & 127;
        float ss  = S[mm] * S[nn];
        float num = fmaf(Q[mm], Q[nn], fmaf(2.0f * EPS, ss, ff_e2 + EPS));
        float den = ss + (ff_e + EPS);
        float r   = __fdividef(num, den) + EPS;
        ob[idx] = r * invLd[nn];
    }
}

extern "C" void kernel_launch(void* const* d_in, const int* in_sizes, int n_in,
                              void* d_out, int out_size) {
    const float* x = (const float*)d_in[0];
    float* out = (float*)d_out;
    int B = in_sizes[0] / CF;   // = 2
    causality_kernel<<<B, 1024>>>(x, out);
}

// round 3
// speedup vs baseline: 1.5913x; 1.2933x over previous
#include <cuda_runtime.h>

// x (2,128,7,7) fp32 -> causality maps (2,128,128) fp32.
// p=1 => Lehmer cross-sums are rank-1 separable:
//   sum_ij cross = S[m]*S[n], sum_ij cross^2 = Q[m]*Q[n].
// Latency-bound problem: spread across 64 blocks, each redundantly computing
// the tiny reduction (L2-resident after first touch) and writing a 512-element
// output slab in a single iteration per thread.

#define EPS 1e-8f
#define C_CH 128
#define F_SP 49
#define CF (C_CH * F_SP)
#define SLABS 32               // output slabs per batch (512 outputs each)

__global__ __launch_bounds__(512, 1)
void causality_kernel(const float* __restrict__ x, float* __restrict__ out) {
    const int b    = blockIdx.x >> 5;       // batch
    const int slab = blockIdx.x & (SLABS - 1);
    const int tid  = threadIdx.x;
    const int ch   = tid >> 2;              // channel 0..127 (4 threads each)
    const int l4   = tid & 3;
    const int lid  = tid & 31;
    const int wid  = tid >> 5;              // 16 warps

    __shared__ float S[C_CH];
    __shared__ float Q[C_CH];
    __shared__ float invLd[C_CH];
    __shared__ float red[16];

    const float* __restrict__ xc = x + b * CF + ch * F_SP;

    // ---- fused pass: raw max + per-channel raw sum / sum-of-squares ----
    float m = -3.402823466e+38f;
    float s = 0.0f, q = 0.0f;
    #pragma unroll
    for (int i = 0; i < 13; i++) {
        int j = l4 + 4 * i;                 // 0..51, guard to 49
        if (j < F_SP) {
            float v = __ldg(xc + j);
            m = fmaxf(m, v);
            s += v;
            q = fmaf(v, v, q);
        }
    }

    // intra-channel (4-lane) reduce for s,q,m
    #pragma unroll
    for (int o = 1; o < 4; o <<= 1) {
        s += __shfl_xor_sync(0xffffffffu, s, o);
        q += __shfl_xor_sync(0xffffffffu, q, o);
        m = fmaxf(m, __shfl_xor_sync(0xffffffffu, m, o));
    }
    // continue max to full warp
    #pragma unroll
    for (int o = 4; o < 32; o <<= 1)
        m = fmaxf(m, __shfl_xor_sync(0xffffffffu, m, o));
    if (lid == 0) red[wid] = m;
    __syncthreads();

    // every warp redundantly folds the 16 warp maxima (no second barrier)
    float v = red[lid & 15];
    #pragma unroll
    for (int o = 1; o < 16; o <<= 1)
        v = fmaxf(v, __shfl_xor_sync(0xffffffffu, v, o));
    const float inv = __fdividef(1.0f, v + EPS);

    if (l4 == 0) {
        float sn = s * inv;
        float qn = q * inv * inv;
        S[ch] = sn;
        Q[ch] = qn;
        // Ld = (Q + 2 eps S + F eps^2 + eps)/(S + F eps + eps) + eps
        float nd = qn + 2.0f * EPS * sn + (float)F_SP * EPS * EPS + EPS;
        float dd = sn + (float)F_SP * EPS + EPS;
        invLd[ch] = __fdividef(dd, nd + EPS * dd);   // = 1/(nd/dd + eps)
    }
    __syncthreads();

    // ---- combine: this block's 512-element slab, 1 element per thread ----
    const float ff_e2 = (float)(F_SP * F_SP) * EPS * EPS;
    const float ff_e  = (float)(F_SP * F_SP) * EPS;
    int idx = slab * 512 + tid;
    int mm = idx >> 7;
    int nn = idx & 127;
    float ss  = S[mm] * S[nn];
    float num = fmaf(Q[mm], Q[nn], fmaf(2.0f * EPS, ss, ff_e2 + EPS));
    float den = ss + (ff_e + EPS);
    float r   = __fdividef(num, den) + EPS;
    out[b * (C_CH * C_CH) + idx] = r * invLd[nn];
}

extern "C" void kernel_launch(void* const* d_in, const int* in_sizes, int n_in,
                              void* d_out, int out_size) {
    const float* x = (const float*)d_in[0];
    float* out = (float*)d_out;
    int B = in_sizes[0] / CF;   // = 2
    causality_kernel<<<B * SLABS, 512>>>(x, out);
}